// round 9
// baseline (speedup 1.0000x reference)
#include <cuda_runtime.h>
#include <cstdint>

// Problem constants: B=2, T=2048, C=1024, H=16, D=64
__device__ float g_qkv[4096 * 3072];
__device__ float g_attn[4096 * 1024];
__device__ float g_wt[3072 * 1024 + 1024 * 1024];   // W_qkv^T then W_out^T

// ---------------------------------------------------------------------------
// helpers
// ---------------------------------------------------------------------------
static __device__ __forceinline__ uint32_t f2tf32(float f) {
    uint32_t u;
    asm("cvt.rna.tf32.f32 %0, %1;" : "=r"(u) : "f"(f));
    return u;
}
static __device__ __forceinline__ float tf32r(float f) {
    return __uint_as_float(f2tf32(f));
}
static __device__ __forceinline__ void mma_tf32(
    float c[4], uint32_t a0, uint32_t a1, uint32_t a2, uint32_t a3,
    uint32_t b0, uint32_t b1)
{
    asm volatile(
        "mma.sync.aligned.m16n8k8.row.col.f32.tf32.tf32.f32 "
        "{%0,%1,%2,%3}, {%4,%5,%6,%7}, {%8,%9}, {%0,%1,%2,%3};"
        : "+f"(c[0]), "+f"(c[1]), "+f"(c[2]), "+f"(c[3])
        : "r"(a0), "r"(a1), "r"(a2), "r"(a3), "r"(b0), "r"(b1));
}

// ---------------------------------------------------------------------------
// Transpose kernel: out[N,K] = in[K,N].
// ---------------------------------------------------------------------------
__global__ void transpose_kernel(const float* __restrict__ in, float* __restrict__ out,
                                 int R, int Ccols)
{
    __shared__ float tile[32][33];
    int c = blockIdx.x * 32 + threadIdx.x;
    int r0 = blockIdx.y * 32;
#pragma unroll
    for (int i = 0; i < 32; i += 8)
        tile[threadIdx.y + i][threadIdx.x] = in[(size_t)(r0 + threadIdx.y + i) * Ccols + c];
    __syncthreads();
    int oc = blockIdx.y * 32 + threadIdx.x;
    int or0 = blockIdx.x * 32;
#pragma unroll
    for (int i = 0; i < 32; i += 8)
        out[(size_t)(or0 + threadIdx.y + i) * R + oc] = tile[threadIdx.x][threadIdx.y + i];
}

// ---------------------------------------------------------------------------
// mma.sync tf32 GEMM with permuted k-layout: C = A * BT^T + bias
// SMEM k-blocks of 8 stored permuted [0,4,1,5,2,6,3,7] so each fragment's
// (tig, tig+4) pair is one float2 load.
// ---------------------------------------------------------------------------
constexpr int ASTR = 40;   // stride/2 = 20 ≡ 4 (mod 16) -> conflict-free LDS.64
constexpr int GEMM_SMEM = 2 * 2 * 128 * ASTR * (int)sizeof(float);   // 81920

__global__ __launch_bounds__(256)
void gemm_mma_kernel(const float* __restrict__ A, const float* __restrict__ BT,
                     const float* __restrict__ bias, float* __restrict__ C,
                     int M, int N, int K)
{
    extern __shared__ float sm[];
    float* AsBase = sm;
    float* BsBase = sm + 2 * 128 * ASTR;

    const int tid  = threadIdx.x;
    const int wid  = tid >> 5;
    const int lane = tid & 31;
    const int gid  = lane >> 2;
    const int tig  = lane & 3;
    const int warp_m = wid & 1;
    const int warp_n = wid >> 1;

    const int row0 = blockIdx.y * 128;
    const int n0   = blockIdx.x * 128;

    const int arow = tid >> 3;
    const int acol = (tid & 7) * 4;
    // permuted store base for a 4-run starting at acol (within 8-block)
    const int pbase = (acol & ~7) + ((acol >> 2) & 1);
    const float* Ab = A  + (size_t)(row0 + arow) * K + acol;
    const float* Bb = BT + (size_t)(n0  + arow) * K + acol;

    float acc[4][4][4];
#pragma unroll
    for (int mi = 0; mi < 4; mi++)
#pragma unroll
        for (int ni = 0; ni < 4; ni++)
#pragma unroll
            for (int r = 0; r < 4; r++) acc[mi][ni][r] = 0.0f;

    const int nchunk = K / 32;

    // prologue: stage chunk 0 into buffer 0 (permuted)
    {
        float* As = AsBase;
        float* Bs = BsBase;
#pragma unroll
        for (int it = 0; it < 4; it++) {
            float4 va = *(const float4*)(Ab + (size_t)(it * 32) * K);
            float4 vb = *(const float4*)(Bb + (size_t)(it * 32) * K);
            float* ad = &As[(arow + it * 32) * ASTR + pbase];
            float* bd = &Bs[(arow + it * 32) * ASTR + pbase];
            ad[0] = tf32r(va.x); ad[2] = tf32r(va.y); ad[4] = tf32r(va.z); ad[6] = tf32r(va.w);
            bd[0] = tf32r(vb.x); bd[2] = tf32r(vb.y); bd[4] = tf32r(vb.z); bd[6] = tf32r(vb.w);
        }
    }
    __syncthreads();

    for (int c = 0; c < nchunk; c++) {
        const int buf = c & 1;
        const float* As = AsBase + buf * 128 * ASTR;
        const float* Bs = BsBase + buf * 128 * ASTR;

        float4 pa[4], pb[4];
        const bool more = (c + 1 < nchunk);
        if (more) {
            const int k1 = (c + 1) * 32;
#pragma unroll
            for (int it = 0; it < 4; it++) {
                pa[it] = *(const float4*)(Ab + (size_t)(it * 32) * K + k1);
                pb[it] = *(const float4*)(Bb + (size_t)(it * 32) * K + k1);
            }
        }

        const int mbase = warp_m * 64;
        const int nbase = warp_n * 32;
#pragma unroll
        for (int kk = 0; kk < 32; kk += 8) {
            uint32_t afr[4][4];
#pragma unroll
            for (int mi = 0; mi < 4; mi++) {
                const int r = mbase + mi * 16;
                float2 lo = *(const float2*)&As[(r + gid)     * ASTR + kk + tig * 2];
                float2 hi = *(const float2*)&As[(r + gid + 8) * ASTR + kk + tig * 2];
                afr[mi][0] = __float_as_uint(lo.x);
                afr[mi][2] = __float_as_uint(lo.y);
                afr[mi][1] = __float_as_uint(hi.x);
                afr[mi][3] = __float_as_uint(hi.y);
            }
            uint32_t bfr[4][2];
#pragma unroll
            for (int ni = 0; ni < 4; ni++) {
                const int n = nbase + ni * 8 + gid;
                float2 bv = *(const float2*)&Bs[n * ASTR + kk + tig * 2];
                bfr[ni][0] = __float_as_uint(bv.x);
                bfr[ni][1] = __float_as_uint(bv.y);
            }
#pragma unroll
            for (int mi = 0; mi < 4; mi++)
#pragma unroll
                for (int ni = 0; ni < 4; ni++)
                    mma_tf32(acc[mi][ni], afr[mi][0], afr[mi][1], afr[mi][2], afr[mi][3],
                             bfr[ni][0], bfr[ni][1]);
        }

        if (more) {
            float* Asn = AsBase + ((c + 1) & 1) * 128 * ASTR;
            float* Bsn = BsBase + ((c + 1) & 1) * 128 * ASTR;
#pragma unroll
            for (int it = 0; it < 4; it++) {
                float* ad = &Asn[(arow + it * 32) * ASTR + pbase];
                float* bd = &Bsn[(arow + it * 32) * ASTR + pbase];
                ad[0] = tf32r(pa[it].x); ad[2] = tf32r(pa[it].y);
                ad[4] = tf32r(pa[it].z); ad[6] = tf32r(pa[it].w);
                bd[0] = tf32r(pb[it].x); bd[2] = tf32r(pb[it].y);
                bd[4] = tf32r(pb[it].z); bd[6] = tf32r(pb[it].w);
            }
            __syncthreads();
        }
    }

#pragma unroll
    for (int mi = 0; mi < 4; mi++) {
        const int r = row0 + warp_m * 64 + mi * 16 + gid;
#pragma unroll
        for (int ni = 0; ni < 4; ni++) {
            const int cc = n0 + warp_n * 32 + ni * 8 + tig * 2;
            const float b0 = bias[cc], b1 = bias[cc + 1];
            float2 v0 = { acc[mi][ni][0] + b0, acc[mi][ni][1] + b1 };
            float2 v1 = { acc[mi][ni][2] + b0, acc[mi][ni][3] + b1 };
            *(float2*)(C + (size_t)r * N + cc)       = v0;
            *(float2*)(C + (size_t)(r + 8) * N + cc) = v1;
        }
    }
}

// ---------------------------------------------------------------------------
// Flash attention (causal) with mma.sync tf32, permuted contraction layout.
// Ks cols (d) permuted, Vst cols (key) permuted, Ps cols permuted (d for Q,
// key for P). Output dims plain.
// ---------------------------------------------------------------------------
constexpr int KSTR = 72;   // stride/2 = 36 ≡ 4 (mod 16)
constexpr int FL2_SMEM = (64 * KSTR + 64 * KSTR + 128 * KSTR) * (int)sizeof(float); // 73728

__global__ __launch_bounds__(256, 2)
void flash_mma_kernel(const float* __restrict__ qkv, float* __restrict__ out)
{
    extern __shared__ float sm[];
    float* Ks  = sm;                    // [64][KSTR]  K[key][d-perm]
    float* Vst = sm + 64 * KSTR;        // [64][KSTR]  V^T[d][key-perm]
    float* Ps  = sm + 128 * KSTR;       // [128][KSTR] staging (Q d-perm / P key-perm)

    const int tid  = threadIdx.x;
    const int wid  = tid >> 5;
    const int lane = tid & 31;
    const int gid  = lane >> 2;
    const int tig  = lane & 3;

    const int qx = 15 - blockIdx.x;     // heavy tiles first
    const int bh = blockIdx.y;
    const int b  = bh >> 4;
    const int h  = bh & 15;
    const int q0 = qx * 128;
    const int rs = 3072;
    const float* base = qkv + (size_t)(b * 2048) * rs + h * 64;

    // ---- stage Q tile (scaled by 1/8, tf32, d-permuted) ----
#pragma unroll
    for (int i = 0; i < 8; i++) {
        int idx = tid + i * 256;
        int row = idx >> 4;
        int dg  = (idx & 15) * 4;
        float4 v = *(const float4*)(base + (size_t)(q0 + row) * rs + dg);
        float* d = &Ps[row * KSTR + (dg & ~7) + ((dg >> 2) & 1)];
        d[0] = tf32r(v.x * 0.125f); d[2] = tf32r(v.y * 0.125f);
        d[4] = tf32r(v.z * 0.125f); d[6] = tf32r(v.w * 0.125f);
    }
    __syncthreads();

    const int lr0 = wid * 16 + gid;
    const int lr1 = lr0 + 8;
    uint32_t qf[8][4];
#pragma unroll
    for (int kk = 0; kk < 8; kk++) {
        float2 lo = *(const float2*)&Ps[lr0 * KSTR + kk * 8 + tig * 2];
        float2 hi = *(const float2*)&Ps[lr1 * KSTR + kk * 8 + tig * 2];
        qf[kk][0] = __float_as_uint(lo.x);
        qf[kk][2] = __float_as_uint(lo.y);
        qf[kk][1] = __float_as_uint(hi.x);
        qf[kk][3] = __float_as_uint(hi.y);
    }

    float of[8][4];
#pragma unroll
    for (int ni = 0; ni < 8; ni++)
#pragma unroll
        for (int r = 0; r < 4; r++) of[ni][r] = 0.0f;
    float m0 = -1e30f, m1 = -1e30f, l0 = 0.0f, l1 = 0.0f;

    const int row0g = q0 + lr0;
    const int row1g = row0g + 8;
    const int key   = tid >> 2;          // one key per thread for K/V load
    const int k7    = key & 7;
    const int pkey  = (key & ~7) + ((k7 < 4) ? (k7 * 2) : ((k7 - 4) * 2 + 1));
    const int dbase = (tid & 3) * 16;
    // P staging permuted positions for cols (2tig, 2tig+1): p0 and p0+2
    const int p0 = (tig & 1) * 4 + (tig >> 1);
    const int nkt = 2 * qx + 2;

    for (int kt = 0; kt < nkt; kt++) {
        __syncthreads();
        // ---- load K -> Ks[key][d-perm], V -> Vst[d][key-perm] ----
        {
            const float* krow = base + (size_t)(kt * 64 + key) * rs + 1024 + dbase;
            const float* vrow = krow + 1024;
#pragma unroll
            for (int i = 0; i < 4; i++) {
                const int dd = dbase + i * 4;
                float4 kv = *(const float4*)(krow + i * 4);
                float* kd = &Ks[key * KSTR + (dd & ~7) + ((dd >> 2) & 1)];
                kd[0] = tf32r(kv.x); kd[2] = tf32r(kv.y);
                kd[4] = tf32r(kv.z); kd[6] = tf32r(kv.w);
                float4 vv = *(const float4*)(vrow + i * 4);
                Vst[(dd + 0) * KSTR + pkey] = tf32r(vv.x);
                Vst[(dd + 1) * KSTR + pkey] = tf32r(vv.y);
                Vst[(dd + 2) * KSTR + pkey] = tf32r(vv.z);
                Vst[(dd + 3) * KSTR + pkey] = tf32r(vv.w);
            }
        }
        __syncthreads();

        // ---- S = Q K^T ----
        float sf[8][4];
#pragma unroll
        for (int ni = 0; ni < 8; ni++)
#pragma unroll
            for (int r = 0; r < 4; r++) sf[ni][r] = 0.0f;

#pragma unroll
        for (int kk = 0; kk < 8; kk++) {
#pragma unroll
            for (int ni = 0; ni < 8; ni++) {
                float2 bv = *(const float2*)&Ks[(ni * 8 + gid) * KSTR + kk * 8 + tig * 2];
                mma_tf32(sf[ni], qf[kk][0], qf[kk][1], qf[kk][2], qf[kk][3],
                         __float_as_uint(bv.x), __float_as_uint(bv.y));
            }
        }

        // ---- causal mask (diagonal tiles only) ----
        if (kt >= 2 * qx) {
            const int cb = kt * 64 + tig * 2;
#pragma unroll
            for (int ni = 0; ni < 8; ni++) {
                const int c0 = cb + ni * 8, c1 = c0 + 1;
                if (c0 > row0g) sf[ni][0] = -1e30f;
                if (c1 > row0g) sf[ni][1] = -1e30f;
                if (c0 > row1g) sf[ni][2] = -1e30f;
                if (c1 > row1g) sf[ni][3] = -1e30f;
            }
        }

        // ---- online softmax ----
        float mx0 = -1e30f, mx1 = -1e30f;
#pragma unroll
        for (int ni = 0; ni < 8; ni++) {
            mx0 = fmaxf(mx0, fmaxf(sf[ni][0], sf[ni][1]));
            mx1 = fmaxf(mx1, fmaxf(sf[ni][2], sf[ni][3]));
        }
        mx0 = fmaxf(mx0, __shfl_xor_sync(0xffffffffu, mx0, 1));
        mx0 = fmaxf(mx0, __shfl_xor_sync(0xffffffffu, mx0, 2));
        mx1 = fmaxf(mx1, __shfl_xor_sync(0xffffffffu, mx1, 1));
        mx1 = fmaxf(mx1, __shfl_xor_sync(0xffffffffu, mx1, 2));

        const float mn0 = fmaxf(m0, mx0);
        const float mn1 = fmaxf(m1, mx1);
        const float corr0 = __expf(m0 - mn0);
        const float corr1 = __expf(m1 - mn1);
        m0 = mn0; m1 = mn1;

        float ls0 = 0.0f, ls1 = 0.0f;
#pragma unroll
        for (int ni = 0; ni < 8; ni++) {
            sf[ni][0] = __expf(sf[ni][0] - mn0); ls0 += sf[ni][0];
            sf[ni][1] = __expf(sf[ni][1] - mn0); ls0 += sf[ni][1];
            sf[ni][2] = __expf(sf[ni][2] - mn1); ls1 += sf[ni][2];
            sf[ni][3] = __expf(sf[ni][3] - mn1); ls1 += sf[ni][3];
        }
        ls0 += __shfl_xor_sync(0xffffffffu, ls0, 1);
        ls0 += __shfl_xor_sync(0xffffffffu, ls0, 2);
        ls1 += __shfl_xor_sync(0xffffffffu, ls1, 1);
        ls1 += __shfl_xor_sync(0xffffffffu, ls1, 2);
        l0 = l0 * corr0 + ls0;
        l1 = l1 * corr1 + ls1;

#pragma unroll
        for (int ni = 0; ni < 8; ni++) {
            of[ni][0] *= corr0; of[ni][1] *= corr0;
            of[ni][2] *= corr1; of[ni][3] *= corr1;
        }

        // ---- stage P (tf32, key-permuted): cols (2tig,2tig+1) -> p0, p0+2 ----
#pragma unroll
        for (int ni = 0; ni < 8; ni++) {
            float* pr0 = &Ps[lr0 * KSTR + ni * 8 + p0];
            float* pr1 = &Ps[lr1 * KSTR + ni * 8 + p0];
            pr0[0] = tf32r(sf[ni][0]); pr0[2] = tf32r(sf[ni][1]);
            pr1[0] = tf32r(sf[ni][2]); pr1[2] = tf32r(sf[ni][3]);
        }
        __syncthreads();

        // ---- O += P V ----
#pragma unroll
        for (int kk = 0; kk < 8; kk++) {
            float2 plo = *(const float2*)&Ps[lr0 * KSTR + kk * 8 + tig * 2];
            float2 phi = *(const float2*)&Ps[lr1 * KSTR + kk * 8 + tig * 2];
            uint32_t pa0 = __float_as_uint(plo.x);
            uint32_t pa2 = __float_as_uint(plo.y);
            uint32_t pa1 = __float_as_uint(phi.x);
            uint32_t pa3 = __float_as_uint(phi.y);
#pragma unroll
            for (int ni = 0; ni < 8; ni++) {
                float2 bv = *(const float2*)&Vst[(ni * 8 + gid) * KSTR + kk * 8 + tig * 2];
                mma_tf32(of[ni], pa0, pa1, pa2, pa3,
                         __float_as_uint(bv.x), __float_as_uint(bv.y));
            }
        }
    }

    // ---- epilogue ----
    const float inv0 = 1.0f / l0;
    const float inv1 = 1.0f / l1;
    float* o0 = out + (size_t)(b * 2048 + row0g) * 1024 + h * 64;
    float* o1 = o0 + (size_t)8 * 1024;
#pragma unroll
    for (int ni = 0; ni < 8; ni++) {
        float2 v0 = { of[ni][0] * inv0, of[ni][1] * inv0 };
        float2 v1 = { of[ni][2] * inv1, of[ni][3] * inv1 };
        *(float2*)(o0 + ni * 8 + tig * 2) = v0;
        *(float2*)(o1 + ni * 8 + tig * 2) = v1;
    }
}

// ---------------------------------------------------------------------------
// kernel_launch
// ---------------------------------------------------------------------------
extern "C" void kernel_launch(void* const* d_in, const int* in_sizes, int n_in,
                              void* d_out, int out_size)
{
    const float* x     = (const float*)d_in[0];   // [4096, 1024]
    const float* w_qkv = (const float*)d_in[1];   // [1024, 3072]
    const float* b_qkv = (const float*)d_in[2];   // [3072]
    const float* w_out = (const float*)d_in[3];   // [1024, 1024]
    const float* b_out = (const float*)d_in[4];   // [1024]
    float* out = (float*)d_out;                   // [4096, 1024]

    float *qkv = nullptr, *attn = nullptr, *wt = nullptr;
    cudaGetSymbolAddress((void**)&qkv,  g_qkv);
    cudaGetSymbolAddress((void**)&attn, g_attn);
    cudaGetSymbolAddress((void**)&wt,   g_wt);
    float* wt_qkv = wt;                      // [3072, 1024]
    float* wt_out = wt + 3072 * 1024;        // [1024, 1024]

    cudaFuncSetAttribute(gemm_mma_kernel,
                         cudaFuncAttributeMaxDynamicSharedMemorySize, GEMM_SMEM);
    cudaFuncSetAttribute(flash_mma_kernel,
                         cudaFuncAttributeMaxDynamicSharedMemorySize, FL2_SMEM);

    // 0) transpose weights
    {
        dim3 blk(32, 8);
        transpose_kernel<<<dim3(3072 / 32, 1024 / 32), blk>>>(w_qkv, wt_qkv, 1024, 3072);
        transpose_kernel<<<dim3(1024 / 32, 1024 / 32), blk>>>(w_out, wt_out, 1024, 1024);
    }

    // 1) QKV projection (mma.sync tf32)
    {
        dim3 grid(3072 / 128, 4096 / 128);
        gemm_mma_kernel<<<grid, 256, GEMM_SMEM>>>(x, wt_qkv, b_qkv, qkv, 4096, 3072, 1024);
    }

    // 2) Causal flash attention (mma.sync tf32) -> g_attn
    {
        dim3 grid(16, 2 * 16);   // (q tiles of 128, B*H)
        flash_mma_kernel<<<grid, 256, FL2_SMEM>>>(qkv, attn);
    }

    // 3) Output projection (mma.sync tf32)
    {
        dim3 grid(1024 / 128, 4096 / 128);
        gemm_mma_kernel<<<grid, 256, GEMM_SMEM>>>(attn, wt_out, b_out, out, 4096, 1024, 1024);
    }
}

// round 10
// speedup vs baseline: 1.0279x; 1.0279x over previous
#include <cuda_runtime.h>
#include <cstdint>

// Problem constants: B=2, T=2048, C=1024, H=16, D=64
__device__ float g_qkv[4096 * 3072];
__device__ float g_attn[4096 * 1024];
__device__ float g_wt[3072 * 1024 + 1024 * 1024];   // W_qkv^T then W_out^T

// ---------------------------------------------------------------------------
// helpers
// ---------------------------------------------------------------------------
static __device__ __forceinline__ uint32_t f2tf32(float f) {
    uint32_t u;
    asm("cvt.rna.tf32.f32 %0, %1;" : "=r"(u) : "f"(f));
    return u;
}
static __device__ __forceinline__ float tf32r(float f) {
    return __uint_as_float(f2tf32(f));
}
static __device__ __forceinline__ void mma_tf32(
    float c[4], uint32_t a0, uint32_t a1, uint32_t a2, uint32_t a3,
    uint32_t b0, uint32_t b1)
{
    asm volatile(
        "mma.sync.aligned.m16n8k8.row.col.f32.tf32.tf32.f32 "
        "{%0,%1,%2,%3}, {%4,%5,%6,%7}, {%8,%9}, {%0,%1,%2,%3};"
        : "+f"(c[0]), "+f"(c[1]), "+f"(c[2]), "+f"(c[3])
        : "r"(a0), "r"(a1), "r"(a2), "r"(a3), "r"(b0), "r"(b1));
}

// ---------------------------------------------------------------------------
// Transpose kernel: out[N,K] = in[K,N].
// ---------------------------------------------------------------------------
__global__ void transpose_kernel(const float* __restrict__ in, float* __restrict__ out,
                                 int R, int Ccols)
{
    __shared__ float tile[32][33];
    int c = blockIdx.x * 32 + threadIdx.x;
    int r0 = blockIdx.y * 32;
#pragma unroll
    for (int i = 0; i < 32; i += 8)
        tile[threadIdx.y + i][threadIdx.x] = in[(size_t)(r0 + threadIdx.y + i) * Ccols + c];
    __syncthreads();
    int oc = blockIdx.y * 32 + threadIdx.x;
    int or0 = blockIdx.x * 32;
#pragma unroll
    for (int i = 0; i < 32; i += 8)
        out[(size_t)(or0 + threadIdx.y + i) * R + oc] = tile[threadIdx.x][threadIdx.y + i];
}

// ---------------------------------------------------------------------------
// mma.sync tf32 GEMM (R8 version, known good): C = A * BT^T + bias
// ---------------------------------------------------------------------------
constexpr int ASTR = 36;
constexpr int GEMM_SMEM = 2 * 2 * 128 * ASTR * (int)sizeof(float);

__global__ __launch_bounds__(256)
void gemm_mma_kernel(const float* __restrict__ A, const float* __restrict__ BT,
                     const float* __restrict__ bias, float* __restrict__ C,
                     int M, int N, int K)
{
    extern __shared__ float sm[];
    float* AsBase = sm;
    float* BsBase = sm + 2 * 128 * ASTR;

    const int tid  = threadIdx.x;
    const int wid  = tid >> 5;
    const int lane = tid & 31;
    const int gid  = lane >> 2;
    const int tig  = lane & 3;
    const int warp_m = wid & 1;
    const int warp_n = wid >> 1;

    const int row0 = blockIdx.y * 128;
    const int n0   = blockIdx.x * 128;

    const int arow = tid >> 3;
    const int acol = (tid & 7) * 4;
    const float* Ab = A  + (size_t)(row0 + arow) * K + acol;
    const float* Bb = BT + (size_t)(n0  + arow) * K + acol;

    float acc[4][4][4];
#pragma unroll
    for (int mi = 0; mi < 4; mi++)
#pragma unroll
        for (int ni = 0; ni < 4; ni++)
#pragma unroll
            for (int r = 0; r < 4; r++) acc[mi][ni][r] = 0.0f;

    const int nchunk = K / 32;

    {
        float* As = AsBase;
        float* Bs = BsBase;
#pragma unroll
        for (int it = 0; it < 4; it++) {
            float4 va = *(const float4*)(Ab + (size_t)(it * 32) * K);
            float4 vb = *(const float4*)(Bb + (size_t)(it * 32) * K);
            float* ad = &As[(arow + it * 32) * ASTR + acol];
            float* bd = &Bs[(arow + it * 32) * ASTR + acol];
            ad[0] = tf32r(va.x); ad[1] = tf32r(va.y); ad[2] = tf32r(va.z); ad[3] = tf32r(va.w);
            bd[0] = tf32r(vb.x); bd[1] = tf32r(vb.y); bd[2] = tf32r(vb.z); bd[3] = tf32r(vb.w);
        }
    }
    __syncthreads();

    for (int c = 0; c < nchunk; c++) {
        const int buf = c & 1;
        const float* As = AsBase + buf * 128 * ASTR;
        const float* Bs = BsBase + buf * 128 * ASTR;

        float4 pa[4], pb[4];
        const bool more = (c + 1 < nchunk);
        if (more) {
            const int k1 = (c + 1) * 32;
#pragma unroll
            for (int it = 0; it < 4; it++) {
                pa[it] = *(const float4*)(Ab + (size_t)(it * 32) * K + k1);
                pb[it] = *(const float4*)(Bb + (size_t)(it * 32) * K + k1);
            }
        }

        const int mbase = warp_m * 64;
        const int nbase = warp_n * 32;
#pragma unroll
        for (int kk = 0; kk < 32; kk += 8) {
            uint32_t afr[4][4];
#pragma unroll
            for (int mi = 0; mi < 4; mi++) {
                const int r = mbase + mi * 16;
                afr[mi][0] = __float_as_uint(As[(r + gid)     * ASTR + kk + tig]);
                afr[mi][1] = __float_as_uint(As[(r + gid + 8) * ASTR + kk + tig]);
                afr[mi][2] = __float_as_uint(As[(r + gid)     * ASTR + kk + tig + 4]);
                afr[mi][3] = __float_as_uint(As[(r + gid + 8) * ASTR + kk + tig + 4]);
            }
            uint32_t bfr[4][2];
#pragma unroll
            for (int ni = 0; ni < 4; ni++) {
                const int n = nbase + ni * 8 + gid;
                bfr[ni][0] = __float_as_uint(Bs[n * ASTR + kk + tig]);
                bfr[ni][1] = __float_as_uint(Bs[n * ASTR + kk + tig + 4]);
            }
#pragma unroll
            for (int mi = 0; mi < 4; mi++)
#pragma unroll
                for (int ni = 0; ni < 4; ni++)
                    mma_tf32(acc[mi][ni], afr[mi][0], afr[mi][1], afr[mi][2], afr[mi][3],
                             bfr[ni][0], bfr[ni][1]);
        }

        if (more) {
            float* Asn = AsBase + ((c + 1) & 1) * 128 * ASTR;
            float* Bsn = BsBase + ((c + 1) & 1) * 128 * ASTR;
#pragma unroll
            for (int it = 0; it < 4; it++) {
                float* ad = &Asn[(arow + it * 32) * ASTR + acol];
                float* bd = &Bsn[(arow + it * 32) * ASTR + acol];
                ad[0] = tf32r(pa[it].x); ad[1] = tf32r(pa[it].y);
                ad[2] = tf32r(pa[it].z); ad[3] = tf32r(pa[it].w);
                bd[0] = tf32r(pb[it].x); bd[1] = tf32r(pb[it].y);
                bd[2] = tf32r(pb[it].z); bd[3] = tf32r(pb[it].w);
            }
            __syncthreads();
        }
    }

#pragma unroll
    for (int mi = 0; mi < 4; mi++) {
        const int r = row0 + warp_m * 64 + mi * 16 + gid;
#pragma unroll
        for (int ni = 0; ni < 4; ni++) {
            const int cc = n0 + warp_n * 32 + ni * 8 + tig * 2;
            const float b0 = bias[cc], b1 = bias[cc + 1];
            float2 v0 = { acc[mi][ni][0] + b0, acc[mi][ni][1] + b1 };
            float2 v1 = { acc[mi][ni][2] + b0, acc[mi][ni][3] + b1 };
            *(float2*)(C + (size_t)r * N + cc)       = v0;
            *(float2*)(C + (size_t)(r + 8) * N + cc) = v1;
        }
    }
}

// ---------------------------------------------------------------------------
// Flash attention (causal) with mma.sync tf32 — 64-row Q tiles, 4 warps.
// Same per-warp math as R8 (16 rows/warp, 64-key tiles), but 4 CTAs/SM
// for latency hiding and 1024-CTA grid for wave balance.
// ---------------------------------------------------------------------------
constexpr int KSTR = 68;
constexpr int FL3_SMEM = (64 + 64 + 64) * KSTR * (int)sizeof(float);  // 52224

__global__ __launch_bounds__(128, 4)
void flash_mma_kernel(const float* __restrict__ qkv, float* __restrict__ out)
{
    extern __shared__ float sm[];
    float* Ks  = sm;                    // [64][KSTR]  K[key][d]
    float* Vst = sm + 64 * KSTR;        // [64][KSTR]  V^T[d][key]
    float* Ps  = sm + 128 * KSTR;       // [64][KSTR]  staging (Q then P)

    const int tid  = threadIdx.x;
    const int wid  = tid >> 5;          // 0..3
    const int lane = tid & 31;
    const int gid  = lane >> 2;
    const int tig  = lane & 3;

    const int qx = 31 - blockIdx.x;     // heavy tiles first
    const int bh = blockIdx.y;
    const int b  = bh >> 4;
    const int h  = bh & 15;
    const int q0 = qx * 64;
    const int rs = 3072;
    const float* base = qkv + (size_t)(b * 2048) * rs + h * 64;

    // ---- stage Q tile (scaled by 1/8, tf32) into Ps ----
#pragma unroll
    for (int i = 0; i < 8; i++) {
        int idx = tid + i * 128;
        int row = idx >> 4;
        int dg  = (idx & 15) * 4;
        float4 v = *(const float4*)(base + (size_t)(q0 + row) * rs + dg);
        float* d = &Ps[row * KSTR + dg];
        d[0] = tf32r(v.x * 0.125f); d[1] = tf32r(v.y * 0.125f);
        d[2] = tf32r(v.z * 0.125f); d[3] = tf32r(v.w * 0.125f);
    }
    __syncthreads();

    const int lr0 = wid * 16 + gid;     // local rows this thread owns
    const int lr1 = lr0 + 8;
    uint32_t qf[8][4];
#pragma unroll
    for (int kk = 0; kk < 8; kk++) {
        qf[kk][0] = __float_as_uint(Ps[lr0 * KSTR + kk * 8 + tig]);
        qf[kk][1] = __float_as_uint(Ps[lr1 * KSTR + kk * 8 + tig]);
        qf[kk][2] = __float_as_uint(Ps[lr0 * KSTR + kk * 8 + tig + 4]);
        qf[kk][3] = __float_as_uint(Ps[lr1 * KSTR + kk * 8 + tig + 4]);
    }

    float of[8][4];
#pragma unroll
    for (int ni = 0; ni < 8; ni++)
#pragma unroll
        for (int r = 0; r < 4; r++) of[ni][r] = 0.0f;
    float m0 = -1e30f, m1 = -1e30f, l0 = 0.0f, l1 = 0.0f;

    const int row0g = q0 + lr0;         // global rows
    const int row1g = row0g + 8;
    const int key   = tid >> 1;         // cooperative K/V load: 2 threads/key
    const int dbase = (tid & 1) * 32;
    const int nkt   = qx + 1;

    for (int kt = 0; kt < nkt; kt++) {
        __syncthreads();   // prior iteration done reading Ks/Vst/Ps
        // ---- load K tile -> Ks[key][d], V tile -> Vst[d][key] (tf32) ----
        {
            const float* krow = base + (size_t)(kt * 64 + key) * rs + 1024 + dbase;
            const float* vrow = krow + 1024;
#pragma unroll
            for (int i = 0; i < 8; i++) {
                float4 kv = *(const float4*)(krow + i * 4);
                float* kd = &Ks[key * KSTR + dbase + i * 4];
                kd[0] = tf32r(kv.x); kd[1] = tf32r(kv.y);
                kd[2] = tf32r(kv.z); kd[3] = tf32r(kv.w);
                float4 vv = *(const float4*)(vrow + i * 4);
                Vst[(dbase + i * 4 + 0) * KSTR + key] = tf32r(vv.x);
                Vst[(dbase + i * 4 + 1) * KSTR + key] = tf32r(vv.y);
                Vst[(dbase + i * 4 + 2) * KSTR + key] = tf32r(vv.z);
                Vst[(dbase + i * 4 + 3) * KSTR + key] = tf32r(vv.w);
            }
        }
        __syncthreads();

        // ---- S = Q K^T ----
        float sf[8][4];
#pragma unroll
        for (int ni = 0; ni < 8; ni++)
#pragma unroll
            for (int r = 0; r < 4; r++) sf[ni][r] = 0.0f;

#pragma unroll
        for (int kk = 0; kk < 8; kk++) {
            uint32_t bfr[8][2];
#pragma unroll
            for (int ni = 0; ni < 8; ni++) {
                bfr[ni][0] = __float_as_uint(Ks[(ni * 8 + gid) * KSTR + kk * 8 + tig]);
                bfr[ni][1] = __float_as_uint(Ks[(ni * 8 + gid) * KSTR + kk * 8 + tig + 4]);
            }
#pragma unroll
            for (int ni = 0; ni < 8; ni++)
                mma_tf32(sf[ni], qf[kk][0], qf[kk][1], qf[kk][2], qf[kk][3],
                         bfr[ni][0], bfr[ni][1]);
        }

        // ---- causal mask (diagonal tile only) ----
        if (kt == qx) {
            const int cb = kt * 64 + tig * 2;
#pragma unroll
            for (int ni = 0; ni < 8; ni++) {
                const int c0 = cb + ni * 8, c1 = c0 + 1;
                if (c0 > row0g) sf[ni][0] = -1e30f;
                if (c1 > row0g) sf[ni][1] = -1e30f;
                if (c0 > row1g) sf[ni][2] = -1e30f;
                if (c1 > row1g) sf[ni][3] = -1e30f;
            }
        }

        // ---- online softmax ----
        float mx0 = -1e30f, mx1 = -1e30f;
#pragma unroll
        for (int ni = 0; ni < 8; ni++) {
            mx0 = fmaxf(mx0, fmaxf(sf[ni][0], sf[ni][1]));
            mx1 = fmaxf(mx1, fmaxf(sf[ni][2], sf[ni][3]));
        }
        mx0 = fmaxf(mx0, __shfl_xor_sync(0xffffffffu, mx0, 1));
        mx0 = fmaxf(mx0, __shfl_xor_sync(0xffffffffu, mx0, 2));
        mx1 = fmaxf(mx1, __shfl_xor_sync(0xffffffffu, mx1, 1));
        mx1 = fmaxf(mx1, __shfl_xor_sync(0xffffffffu, mx1, 2));

        const float mn0 = fmaxf(m0, mx0);
        const float mn1 = fmaxf(m1, mx1);
        const float corr0 = __expf(m0 - mn0);
        const float corr1 = __expf(m1 - mn1);
        m0 = mn0; m1 = mn1;

        float ls0 = 0.0f, ls1 = 0.0f;
#pragma unroll
        for (int ni = 0; ni < 8; ni++) {
            sf[ni][0] = __expf(sf[ni][0] - mn0); ls0 += sf[ni][0];
            sf[ni][1] = __expf(sf[ni][1] - mn0); ls0 += sf[ni][1];
            sf[ni][2] = __expf(sf[ni][2] - mn1); ls1 += sf[ni][2];
            sf[ni][3] = __expf(sf[ni][3] - mn1); ls1 += sf[ni][3];
        }
        ls0 += __shfl_xor_sync(0xffffffffu, ls0, 1);
        ls0 += __shfl_xor_sync(0xffffffffu, ls0, 2);
        ls1 += __shfl_xor_sync(0xffffffffu, ls1, 1);
        ls1 += __shfl_xor_sync(0xffffffffu, ls1, 2);
        l0 = l0 * corr0 + ls0;
        l1 = l1 * corr1 + ls1;

#pragma unroll
        for (int ni = 0; ni < 8; ni++) {
            of[ni][0] *= corr0; of[ni][1] *= corr0;
            of[ni][2] *= corr1; of[ni][3] *= corr1;
        }

        // ---- stage P (tf32) for A-operand re-fragmentation ----
#pragma unroll
        for (int ni = 0; ni < 8; ni++) {
            float2 p0 = { tf32r(sf[ni][0]), tf32r(sf[ni][1]) };
            float2 p1 = { tf32r(sf[ni][2]), tf32r(sf[ni][3]) };
            *(float2*)&Ps[lr0 * KSTR + ni * 8 + tig * 2] = p0;
            *(float2*)&Ps[lr1 * KSTR + ni * 8 + tig * 2] = p1;
        }
        __syncthreads();

        // ---- O += P V ----
#pragma unroll
        for (int kk = 0; kk < 8; kk++) {
            uint32_t pa0 = __float_as_uint(Ps[lr0 * KSTR + kk * 8 + tig]);
            uint32_t pa1 = __float_as_uint(Ps[lr1 * KSTR + kk * 8 + tig]);
            uint32_t pa2 = __float_as_uint(Ps[lr0 * KSTR + kk * 8 + tig + 4]);
            uint32_t pa3 = __float_as_uint(Ps[lr1 * KSTR + kk * 8 + tig + 4]);
#pragma unroll
            for (int ni = 0; ni < 8; ni++) {
                uint32_t b0 = __float_as_uint(Vst[(ni * 8 + gid) * KSTR + kk * 8 + tig]);
                uint32_t b1 = __float_as_uint(Vst[(ni * 8 + gid) * KSTR + kk * 8 + tig + 4]);
                mma_tf32(of[ni], pa0, pa1, pa2, pa3, b0, b1);
            }
        }
    }

    // ---- epilogue ----
    const float inv0 = 1.0f / l0;
    const float inv1 = 1.0f / l1;
    float* o0 = out + (size_t)(b * 2048 + row0g) * 1024 + h * 64;
    float* o1 = o0 + (size_t)8 * 1024;
#pragma unroll
    for (int ni = 0; ni < 8; ni++) {
        float2 v0 = { of[ni][0] * inv0, of[ni][1] * inv0 };
        float2 v1 = { of[ni][2] * inv1, of[ni][3] * inv1 };
        *(float2*)(o0 + ni * 8 + tig * 2) = v0;
        *(float2*)(o1 + ni * 8 + tig * 2) = v1;
    }
}

// ---------------------------------------------------------------------------
// kernel_launch
// ---------------------------------------------------------------------------
extern "C" void kernel_launch(void* const* d_in, const int* in_sizes, int n_in,
                              void* d_out, int out_size)
{
    const float* x     = (const float*)d_in[0];   // [4096, 1024]
    const float* w_qkv = (const float*)d_in[1];   // [1024, 3072]
    const float* b_qkv = (const float*)d_in[2];   // [3072]
    const float* w_out = (const float*)d_in[3];   // [1024, 1024]
    const float* b_out = (const float*)d_in[4];   // [1024]
    float* out = (float*)d_out;                   // [4096, 1024]

    float *qkv = nullptr, *attn = nullptr, *wt = nullptr;
    cudaGetSymbolAddress((void**)&qkv,  g_qkv);
    cudaGetSymbolAddress((void**)&attn, g_attn);
    cudaGetSymbolAddress((void**)&wt,   g_wt);
    float* wt_qkv = wt;                      // [3072, 1024]
    float* wt_out = wt + 3072 * 1024;        // [1024, 1024]

    cudaFuncSetAttribute(gemm_mma_kernel,
                         cudaFuncAttributeMaxDynamicSharedMemorySize, GEMM_SMEM);
    cudaFuncSetAttribute(flash_mma_kernel,
                         cudaFuncAttributeMaxDynamicSharedMemorySize, FL3_SMEM);

    // 0) transpose weights
    {
        dim3 blk(32, 8);
        transpose_kernel<<<dim3(3072 / 32, 1024 / 32), blk>>>(w_qkv, wt_qkv, 1024, 3072);
        transpose_kernel<<<dim3(1024 / 32, 1024 / 32), blk>>>(w_out, wt_out, 1024, 1024);
    }

    // 1) QKV projection (mma.sync tf32)
    {
        dim3 grid(3072 / 128, 4096 / 128);
        gemm_mma_kernel<<<grid, 256, GEMM_SMEM>>>(x, wt_qkv, b_qkv, qkv, 4096, 3072, 1024);
    }

    // 2) Causal flash attention (mma.sync tf32) -> g_attn
    {
        dim3 grid(32, 2 * 16);   // (q tiles of 64, B*H)
        flash_mma_kernel<<<grid, 128, FL3_SMEM>>>(qkv, attn);
    }

    // 3) Output projection (mma.sync tf32)
    {
        dim3 grid(1024 / 128, 4096 / 128);
        gemm_mma_kernel<<<grid, 256, GEMM_SMEM>>>(attn, wt_out, b_out, out, 4096, 1024, 1024);
    }
}

// round 11
// speedup vs baseline: 1.2342x; 1.2007x over previous
#include <cuda_runtime.h>
#include <cstdint>

// Problem constants: B=2, T=2048, C=1024, H=16, D=64
__device__ float g_qkv[4096 * 3072];
__device__ float g_attn[4096 * 1024];
__device__ float g_wt[3072 * 1024 + 1024 * 1024];   // W_qkv^T then W_out^T

// ---------------------------------------------------------------------------
// helpers
// ---------------------------------------------------------------------------
static __device__ __forceinline__ uint32_t f2tf32(float f) {
    uint32_t u;
    asm("cvt.rna.tf32.f32 %0, %1;" : "=r"(u) : "f"(f));
    return u;
}
static __device__ __forceinline__ float tf32r(float f) {
    return __uint_as_float(f2tf32(f));
}
static __device__ __forceinline__ void mma_tf32(
    float c[4], uint32_t a0, uint32_t a1, uint32_t a2, uint32_t a3,
    uint32_t b0, uint32_t b1)
{
    asm volatile(
        "mma.sync.aligned.m16n8k8.row.col.f32.tf32.tf32.f32 "
        "{%0,%1,%2,%3}, {%4,%5,%6,%7}, {%8,%9}, {%0,%1,%2,%3};"
        : "+f"(c[0]), "+f"(c[1]), "+f"(c[2]), "+f"(c[3])
        : "r"(a0), "r"(a1), "r"(a2), "r"(a3), "r"(b0), "r"(b1));
}
static __device__ __forceinline__ uint32_t smem_u32(const void* p) {
    uint32_t a;
    asm("{ .reg .u64 t; cvta.to.shared.u64 t, %1; cvt.u32.u64 %0, t; }"
        : "=r"(a) : "l"(p));
    return a;
}
static __device__ __forceinline__ void cp16(uint32_t dst, const void* src) {
    asm volatile("cp.async.cg.shared.global [%0], [%1], 16;" :: "r"(dst), "l"(src));
}
#define CP_COMMIT() asm volatile("cp.async.commit_group;" ::: "memory")
#define CP_WAIT0()  asm volatile("cp.async.wait_group 0;" ::: "memory")

// ---------------------------------------------------------------------------
// Transpose kernel: out[N,K] = in[K,N].
// ---------------------------------------------------------------------------
__global__ void transpose_kernel(const float* __restrict__ in, float* __restrict__ out,
                                 int R, int Ccols)
{
    __shared__ float tile[32][33];
    int c = blockIdx.x * 32 + threadIdx.x;
    int r0 = blockIdx.y * 32;
#pragma unroll
    for (int i = 0; i < 32; i += 8)
        tile[threadIdx.y + i][threadIdx.x] = in[(size_t)(r0 + threadIdx.y + i) * Ccols + c];
    __syncthreads();
    int oc = blockIdx.y * 32 + threadIdx.x;
    int or0 = blockIdx.x * 32;
#pragma unroll
    for (int i = 0; i < 32; i += 8)
        out[(size_t)(or0 + threadIdx.y + i) * R + oc] = tile[threadIdx.x][threadIdx.y + i];
}

// ---------------------------------------------------------------------------
// mma.sync tf32 GEMM (R8 version): C = A * BT^T + bias
// round_out=1 -> write tf32-rounded outputs (for buffers consumed as tf32).
// ---------------------------------------------------------------------------
constexpr int ASTR = 36;
constexpr int GEMM_SMEM = 2 * 2 * 128 * ASTR * (int)sizeof(float);

__global__ __launch_bounds__(256)
void gemm_mma_kernel(const float* __restrict__ A, const float* __restrict__ BT,
                     const float* __restrict__ bias, float* __restrict__ C,
                     int M, int N, int K, int round_out)
{
    extern __shared__ float sm[];
    float* AsBase = sm;
    float* BsBase = sm + 2 * 128 * ASTR;

    const int tid  = threadIdx.x;
    const int wid  = tid >> 5;
    const int lane = tid & 31;
    const int gid  = lane >> 2;
    const int tig  = lane & 3;
    const int warp_m = wid & 1;
    const int warp_n = wid >> 1;

    const int row0 = blockIdx.y * 128;
    const int n0   = blockIdx.x * 128;

    const int arow = tid >> 3;
    const int acol = (tid & 7) * 4;
    const float* Ab = A  + (size_t)(row0 + arow) * K + acol;
    const float* Bb = BT + (size_t)(n0  + arow) * K + acol;

    float acc[4][4][4];
#pragma unroll
    for (int mi = 0; mi < 4; mi++)
#pragma unroll
        for (int ni = 0; ni < 4; ni++)
#pragma unroll
            for (int r = 0; r < 4; r++) acc[mi][ni][r] = 0.0f;

    const int nchunk = K / 32;

    {
        float* As = AsBase;
        float* Bs = BsBase;
#pragma unroll
        for (int it = 0; it < 4; it++) {
            float4 va = *(const float4*)(Ab + (size_t)(it * 32) * K);
            float4 vb = *(const float4*)(Bb + (size_t)(it * 32) * K);
            float* ad = &As[(arow + it * 32) * ASTR + acol];
            float* bd = &Bs[(arow + it * 32) * ASTR + acol];
            ad[0] = tf32r(va.x); ad[1] = tf32r(va.y); ad[2] = tf32r(va.z); ad[3] = tf32r(va.w);
            bd[0] = tf32r(vb.x); bd[1] = tf32r(vb.y); bd[2] = tf32r(vb.z); bd[3] = tf32r(vb.w);
        }
    }
    __syncthreads();

    for (int c = 0; c < nchunk; c++) {
        const int buf = c & 1;
        const float* As = AsBase + buf * 128 * ASTR;
        const float* Bs = BsBase + buf * 128 * ASTR;

        float4 pa[4], pb[4];
        const bool more = (c + 1 < nchunk);
        if (more) {
            const int k1 = (c + 1) * 32;
#pragma unroll
            for (int it = 0; it < 4; it++) {
                pa[it] = *(const float4*)(Ab + (size_t)(it * 32) * K + k1);
                pb[it] = *(const float4*)(Bb + (size_t)(it * 32) * K + k1);
            }
        }

        const int mbase = warp_m * 64;
        const int nbase = warp_n * 32;
#pragma unroll
        for (int kk = 0; kk < 32; kk += 8) {
            uint32_t afr[4][4];
#pragma unroll
            for (int mi = 0; mi < 4; mi++) {
                const int r = mbase + mi * 16;
                afr[mi][0] = __float_as_uint(As[(r + gid)     * ASTR + kk + tig]);
                afr[mi][1] = __float_as_uint(As[(r + gid + 8) * ASTR + kk + tig]);
                afr[mi][2] = __float_as_uint(As[(r + gid)     * ASTR + kk + tig + 4]);
                afr[mi][3] = __float_as_uint(As[(r + gid + 8) * ASTR + kk + tig + 4]);
            }
            uint32_t bfr[4][2];
#pragma unroll
            for (int ni = 0; ni < 4; ni++) {
                const int n = nbase + ni * 8 + gid;
                bfr[ni][0] = __float_as_uint(Bs[n * ASTR + kk + tig]);
                bfr[ni][1] = __float_as_uint(Bs[n * ASTR + kk + tig + 4]);
            }
#pragma unroll
            for (int mi = 0; mi < 4; mi++)
#pragma unroll
                for (int ni = 0; ni < 4; ni++)
                    mma_tf32(acc[mi][ni], afr[mi][0], afr[mi][1], afr[mi][2], afr[mi][3],
                             bfr[ni][0], bfr[ni][1]);
        }

        if (more) {
            float* Asn = AsBase + ((c + 1) & 1) * 128 * ASTR;
            float* Bsn = BsBase + ((c + 1) & 1) * 128 * ASTR;
#pragma unroll
            for (int it = 0; it < 4; it++) {
                float* ad = &Asn[(arow + it * 32) * ASTR + acol];
                float* bd = &Bsn[(arow + it * 32) * ASTR + acol];
                ad[0] = tf32r(pa[it].x); ad[1] = tf32r(pa[it].y);
                ad[2] = tf32r(pa[it].z); ad[3] = tf32r(pa[it].w);
                bd[0] = tf32r(pb[it].x); bd[1] = tf32r(pb[it].y);
                bd[2] = tf32r(pb[it].z); bd[3] = tf32r(pb[it].w);
            }
            __syncthreads();
        }
    }

#pragma unroll
    for (int mi = 0; mi < 4; mi++) {
        const int r = row0 + warp_m * 64 + mi * 16 + gid;
#pragma unroll
        for (int ni = 0; ni < 4; ni++) {
            const int cc = n0 + warp_n * 32 + ni * 8 + tig * 2;
            const float b0 = bias[cc], b1 = bias[cc + 1];
            float2 v0, v1;
            if (round_out) {
                v0 = make_float2(tf32r(acc[mi][ni][0] + b0), tf32r(acc[mi][ni][1] + b1));
                v1 = make_float2(tf32r(acc[mi][ni][2] + b0), tf32r(acc[mi][ni][3] + b1));
            } else {
                v0 = make_float2(acc[mi][ni][0] + b0, acc[mi][ni][1] + b1);
                v1 = make_float2(acc[mi][ni][2] + b0, acc[mi][ni][3] + b1);
            }
            *(float2*)(C + (size_t)r * N + cc)       = v0;
            *(float2*)(C + (size_t)(r + 8) * N + cc) = v1;
        }
    }
}

// ---------------------------------------------------------------------------
// Flash attention (causal), mma.sync tf32. 128-row Q tiles, 8 warps (R8 shape),
// cp.async double-buffered K/V (qkv pre-rounded to tf32 by QKV epilogue),
// V kept [key][d] (no transpose; B-fragments read directly).
// ---------------------------------------------------------------------------
constexpr int KSTR = 68;
// K bufs (2x 64*KSTR) + V bufs (2x 64*KSTR) + Ps (128*KSTR)
constexpr int FL4_SMEM = (4 * 64 + 128) * KSTR * (int)sizeof(float);   // 104448

__global__ __launch_bounds__(256, 2)
void flash_mma_kernel(const float* __restrict__ qkv, float* __restrict__ out)
{
    extern __shared__ float sm[];
    float* KBuf = sm;                       // [2][64][KSTR]
    float* VBuf = sm + 2 * 64 * KSTR;       // [2][64][KSTR]
    float* Ps   = sm + 4 * 64 * KSTR;       // [128][KSTR]
    const uint32_t kv_smem = smem_u32(sm);

    const int tid  = threadIdx.x;
    const int wid  = tid >> 5;
    const int lane = tid & 31;
    const int gid  = lane >> 2;
    const int tig  = lane & 3;

    const int qx = 15 - blockIdx.x;         // heavy tiles first
    const int bh = blockIdx.y;
    const int b  = bh >> 4;
    const int h  = bh & 15;
    const int q0 = qx * 128;
    const int rs = 3072;
    const float* base = qkv + (size_t)(b * 2048) * rs + h * 64;

    // cp.async mapping: 256 threads, 64 keys -> key = tid>>2, 4 chunks of 16B
    const int ckey = tid >> 2;
    const int c4   = tid & 3;
    const int nkt  = 2 * qx + 2;

    // issue K/V tile 0 into buffer 0
    {
        const char* ksrc = (const char*)(base + (size_t)(0 * 64 + ckey) * rs + 1024);
        const char* vsrc = (const char*)(base + (size_t)(0 * 64 + ckey) * rs + 2048);
        const uint32_t kdst = kv_smem + (uint32_t)(ckey * KSTR) * 4;
        const uint32_t vdst = kdst + (uint32_t)(2 * 64 * KSTR) * 4;
#pragma unroll
        for (int i = 0; i < 4; i++) {
            const int chunk = c4 * 4 + i;
            cp16(kdst + chunk * 16, ksrc + chunk * 16);
            cp16(vdst + chunk * 16, vsrc + chunk * 16);
        }
        CP_COMMIT();
    }

    // ---- stage Q tile (exact x0.125; qkv already tf32-rounded) ----
#pragma unroll
    for (int i = 0; i < 8; i++) {
        int idx = tid + i * 256;
        int row = idx >> 4;
        int dg  = (idx & 15) * 4;
        float4 v = *(const float4*)(base + (size_t)(q0 + row) * rs + dg);
        float* d = &Ps[row * KSTR + dg];
        d[0] = v.x * 0.125f; d[1] = v.y * 0.125f;
        d[2] = v.z * 0.125f; d[3] = v.w * 0.125f;
    }
    __syncthreads();

    const int lr0 = wid * 16 + gid;
    const int lr1 = lr0 + 8;
    uint32_t qf[8][4];
#pragma unroll
    for (int kk = 0; kk < 8; kk++) {
        qf[kk][0] = __float_as_uint(Ps[lr0 * KSTR + kk * 8 + tig]);
        qf[kk][1] = __float_as_uint(Ps[lr1 * KSTR + kk * 8 + tig]);
        qf[kk][2] = __float_as_uint(Ps[lr0 * KSTR + kk * 8 + tig + 4]);
        qf[kk][3] = __float_as_uint(Ps[lr1 * KSTR + kk * 8 + tig + 4]);
    }

    float of[8][4];
#pragma unroll
    for (int ni = 0; ni < 8; ni++)
#pragma unroll
        for (int r = 0; r < 4; r++) of[ni][r] = 0.0f;
    float m0 = -1e30f, m1 = -1e30f, l0 = 0.0f, l1 = 0.0f;

    const int row0g = q0 + lr0;
    const int row1g = row0g + 8;

    for (int kt = 0; kt < nkt; kt++) {
        const int buf = kt & 1;
        const float* Ks = KBuf + buf * 64 * KSTR;
        const float* Vs = VBuf + buf * 64 * KSTR;

        CP_WAIT0();
        __syncthreads();   // kv(kt) visible; prior PV reads of other buf done

        // issue next tile into the other buffer (fully overlapped with compute)
        if (kt + 1 < nkt) {
            const char* ksrc = (const char*)(base + (size_t)((kt + 1) * 64 + ckey) * rs + 1024);
            const char* vsrc = (const char*)(base + (size_t)((kt + 1) * 64 + ckey) * rs + 2048);
            const uint32_t kdst = kv_smem + (uint32_t)(((buf ^ 1) * 64 + ckey) * KSTR) * 4;
            const uint32_t vdst = kdst + (uint32_t)(2 * 64 * KSTR) * 4;
#pragma unroll
            for (int i = 0; i < 4; i++) {
                const int chunk = c4 * 4 + i;
                cp16(kdst + chunk * 16, ksrc + chunk * 16);
                cp16(vdst + chunk * 16, vsrc + chunk * 16);
            }
            CP_COMMIT();
        }

        // ---- S = Q K^T ----
        float sf[8][4];
#pragma unroll
        for (int ni = 0; ni < 8; ni++)
#pragma unroll
            for (int r = 0; r < 4; r++) sf[ni][r] = 0.0f;

#pragma unroll
        for (int kk = 0; kk < 8; kk++) {
            uint32_t bfr[8][2];
#pragma unroll
            for (int ni = 0; ni < 8; ni++) {
                bfr[ni][0] = __float_as_uint(Ks[(ni * 8 + gid) * KSTR + kk * 8 + tig]);
                bfr[ni][1] = __float_as_uint(Ks[(ni * 8 + gid) * KSTR + kk * 8 + tig + 4]);
            }
#pragma unroll
            for (int ni = 0; ni < 8; ni++)
                mma_tf32(sf[ni], qf[kk][0], qf[kk][1], qf[kk][2], qf[kk][3],
                         bfr[ni][0], bfr[ni][1]);
        }

        // ---- causal mask (diagonal tiles only) ----
        if (kt >= 2 * qx) {
            const int cb = kt * 64 + tig * 2;
#pragma unroll
            for (int ni = 0; ni < 8; ni++) {
                const int c0 = cb + ni * 8, c1 = c0 + 1;
                if (c0 > row0g) sf[ni][0] = -1e30f;
                if (c1 > row0g) sf[ni][1] = -1e30f;
                if (c0 > row1g) sf[ni][2] = -1e30f;
                if (c1 > row1g) sf[ni][3] = -1e30f;
            }
        }

        // ---- online softmax ----
        float mx0 = -1e30f, mx1 = -1e30f;
#pragma unroll
        for (int ni = 0; ni < 8; ni++) {
            mx0 = fmaxf(mx0, fmaxf(sf[ni][0], sf[ni][1]));
            mx1 = fmaxf(mx1, fmaxf(sf[ni][2], sf[ni][3]));
        }
        mx0 = fmaxf(mx0, __shfl_xor_sync(0xffffffffu, mx0, 1));
        mx0 = fmaxf(mx0, __shfl_xor_sync(0xffffffffu, mx0, 2));
        mx1 = fmaxf(mx1, __shfl_xor_sync(0xffffffffu, mx1, 1));
        mx1 = fmaxf(mx1, __shfl_xor_sync(0xffffffffu, mx1, 2));

        const float mn0 = fmaxf(m0, mx0);
        const float mn1 = fmaxf(m1, mx1);
        const float corr0 = __expf(m0 - mn0);
        const float corr1 = __expf(m1 - mn1);
        m0 = mn0; m1 = mn1;

        float ls0 = 0.0f, ls1 = 0.0f;
#pragma unroll
        for (int ni = 0; ni < 8; ni++) {
            sf[ni][0] = __expf(sf[ni][0] - mn0); ls0 += sf[ni][0];
            sf[ni][1] = __expf(sf[ni][1] - mn0); ls0 += sf[ni][1];
            sf[ni][2] = __expf(sf[ni][2] - mn1); ls1 += sf[ni][2];
            sf[ni][3] = __expf(sf[ni][3] - mn1); ls1 += sf[ni][3];
        }
        ls0 += __shfl_xor_sync(0xffffffffu, ls0, 1);
        ls0 += __shfl_xor_sync(0xffffffffu, ls0, 2);
        ls1 += __shfl_xor_sync(0xffffffffu, ls1, 1);
        ls1 += __shfl_xor_sync(0xffffffffu, ls1, 2);
        l0 = l0 * corr0 + ls0;
        l1 = l1 * corr1 + ls1;

#pragma unroll
        for (int ni = 0; ni < 8; ni++) {
            of[ni][0] *= corr0; of[ni][1] *= corr0;
            of[ni][2] *= corr1; of[ni][3] *= corr1;
        }

        // ---- stage P (tf32) for A-operand re-fragmentation ----
#pragma unroll
        for (int ni = 0; ni < 8; ni++) {
            float2 p0 = { tf32r(sf[ni][0]), tf32r(sf[ni][1]) };
            float2 p1 = { tf32r(sf[ni][2]), tf32r(sf[ni][3]) };
            *(float2*)&Ps[lr0 * KSTR + ni * 8 + tig * 2] = p0;
            *(float2*)&Ps[lr1 * KSTR + ni * 8 + tig * 2] = p1;
        }
        __syncthreads();

        // ---- O += P V  (V read directly from [key][d] layout) ----
#pragma unroll
        for (int kk = 0; kk < 8; kk++) {
            uint32_t pa0 = __float_as_uint(Ps[lr0 * KSTR + kk * 8 + tig]);
            uint32_t pa1 = __float_as_uint(Ps[lr1 * KSTR + kk * 8 + tig]);
            uint32_t pa2 = __float_as_uint(Ps[lr0 * KSTR + kk * 8 + tig + 4]);
            uint32_t pa3 = __float_as_uint(Ps[lr1 * KSTR + kk * 8 + tig + 4]);
#pragma unroll
            for (int ni = 0; ni < 8; ni++) {
                uint32_t b0 = __float_as_uint(Vs[(kk * 8 + tig)     * KSTR + ni * 8 + gid]);
                uint32_t b1 = __float_as_uint(Vs[(kk * 8 + tig + 4) * KSTR + ni * 8 + gid]);
                mma_tf32(of[ni], pa0, pa1, pa2, pa3, b0, b1);
            }
        }
    }

    // ---- epilogue ----
    const float inv0 = 1.0f / l0;
    const float inv1 = 1.0f / l1;
    float* o0 = out + (size_t)(b * 2048 + row0g) * 1024 + h * 64;
    float* o1 = o0 + (size_t)8 * 1024;
#pragma unroll
    for (int ni = 0; ni < 8; ni++) {
        float2 v0 = { of[ni][0] * inv0, of[ni][1] * inv0 };
        float2 v1 = { of[ni][2] * inv1, of[ni][3] * inv1 };
        *(float2*)(o0 + ni * 8 + tig * 2) = v0;
        *(float2*)(o1 + ni * 8 + tig * 2) = v1;
    }
}

// ---------------------------------------------------------------------------
// kernel_launch
// ---------------------------------------------------------------------------
extern "C" void kernel_launch(void* const* d_in, const int* in_sizes, int n_in,
                              void* d_out, int out_size)
{
    const float* x     = (const float*)d_in[0];   // [4096, 1024]
    const float* w_qkv = (const float*)d_in[1];   // [1024, 3072]
    const float* b_qkv = (const float*)d_in[2];   // [3072]
    const float* w_out = (const float*)d_in[3];   // [1024, 1024]
    const float* b_out = (const float*)d_in[4];   // [1024]
    float* out = (float*)d_out;                   // [4096, 1024]

    float *qkv = nullptr, *attn = nullptr, *wt = nullptr;
    cudaGetSymbolAddress((void**)&qkv,  g_qkv);
    cudaGetSymbolAddress((void**)&attn, g_attn);
    cudaGetSymbolAddress((void**)&wt,   g_wt);
    float* wt_qkv = wt;                      // [3072, 1024]
    float* wt_out = wt + 3072 * 1024;        // [1024, 1024]

    cudaFuncSetAttribute(gemm_mma_kernel,
                         cudaFuncAttributeMaxDynamicSharedMemorySize, GEMM_SMEM);
    cudaFuncSetAttribute(flash_mma_kernel,
                         cudaFuncAttributeMaxDynamicSharedMemorySize, FL4_SMEM);

    // 0) transpose weights
    {
        dim3 blk(32, 8);
        transpose_kernel<<<dim3(3072 / 32, 1024 / 32), blk>>>(w_qkv, wt_qkv, 1024, 3072);
        transpose_kernel<<<dim3(1024 / 32, 1024 / 32), blk>>>(w_out, wt_out, 1024, 1024);
    }

    // 1) QKV projection (tf32-rounded output for flash's cp.async path)
    {
        dim3 grid(3072 / 128, 4096 / 128);
        gemm_mma_kernel<<<grid, 256, GEMM_SMEM>>>(x, wt_qkv, b_qkv, qkv, 4096, 3072, 1024, 1);
    }

    // 2) Causal flash attention (mma.sync tf32, cp.async K/V) -> g_attn
    {
        dim3 grid(16, 2 * 16);   // (q tiles of 128, B*H)
        flash_mma_kernel<<<grid, 256, FL4_SMEM>>>(qkv, attn);
    }

    // 3) Output projection (full-precision output)
    {
        dim3 grid(1024 / 128, 4096 / 128);
        gemm_mma_kernel<<<grid, 256, GEMM_SMEM>>>(attn, wt_out, b_out, out, 4096, 1024, 1024, 0);
    }
}